// round 3
// baseline (speedup 1.0000x reference)
#include <cuda_runtime.h>

#define Nn 40000
#define Mm 10000
#define NNZv 400000
#define FT 128
#define HID 256
#define NCLS 10
#define NG 128
#define BN_EPS 1e-5f

typedef unsigned long long ull;

// ---------------- scratch ----------------
__device__ float g_E[(size_t)Mm * HID];
__device__ float g_P0[(size_t)Nn * HID];   // H(Ht(bn(h0))): layer1 input AND pooled h0
__device__ float g_P1[(size_t)Nn * HID];   // pooled h1; reused as Pa [N,128] in layer0
__device__ float g_Z[(size_t)Nn * HID];
__device__ float g_h0[(size_t)Nn * HID];
__device__ float g_h1[(size_t)Nn * HID];
__device__ float g_dinv[Nn];
__device__ float g_stats[2 * HID];
__device__ float g_bn[2 * HID];            // sc | sh
__device__ float g_out[(size_t)Nn * NCLS];
__device__ float g_segsum[NG * NCLS];
__device__ float g_segcnt[NG];
__device__ int g_ecnt[Mm];
__device__ int g_estart[Mm + 1];
__device__ int g_ecur[Mm];
__device__ int g_elist[NNZv];
__device__ int g_ncnt[Nn];
__device__ int g_nstart[Nn + 1];
__device__ int g_ncur[Nn];
__device__ int g_nlist[NNZv];

// ---------------- f32x2 helpers ----------------
__device__ __forceinline__ ull pk2(float lo, float hi) {
    ull r;
    asm("mov.b64 %0, {%1, %2};" : "=l"(r) : "f"(lo), "f"(hi));
    return r;
}
__device__ __forceinline__ void ffma2(ull& d, ull a, ull b) {
    asm("fma.rn.f32x2 %0, %1, %2, %0;" : "+l"(d) : "l"(a), "l"(b));
}
__device__ __forceinline__ float2 upk(ull v) {
    float2 f;
    asm("mov.b64 {%0, %1}, %2;" : "=f"(f.x), "=f"(f.y) : "l"(v));
    return f;
}

// ---------------- init / utility ----------------
__global__ void k_init(int* ecnt, int* ncnt, float* stats) {
    int i = blockIdx.x * blockDim.x + threadIdx.x;
    int stride = gridDim.x * blockDim.x;
    for (int j = i; j < Mm; j += stride) ecnt[j] = 0;
    for (int j = i; j < Nn; j += stride) ncnt[j] = 0;
    if (i < 2 * HID) stats[i] = 0.f;
}
__global__ void k_zerof(float* p, int n) {
    int i = blockIdx.x * blockDim.x + threadIdx.x;
    if (i < n) p[i] = 0.f;
}

// ---------------- CSR build ----------------
__global__ void k_hist(const int* __restrict__ nidx, const int* __restrict__ eidx,
                       int* __restrict__ ecnt, int* __restrict__ ncnt) {
    int i = blockIdx.x * blockDim.x + threadIdx.x;
    if (i < NNZv) {
        atomicAdd(&ecnt[eidx[i]], 1);
        atomicAdd(&ncnt[nidx[i]], 1);
    }
}

// 2 blocks: block0 scans edges, block1 scans nodes (independent)
__global__ void k_scan2(const int* __restrict__ ecnt, int* __restrict__ estart, int* __restrict__ ecur,
                        const int* __restrict__ ncnt, int* __restrict__ nstart, int* __restrict__ ncur) {
    const int* cnt = blockIdx.x ? ncnt : ecnt;
    int* start = blockIdx.x ? nstart : estart;
    int* cursor = blockIdx.x ? ncur : ecur;
    int n = blockIdx.x ? Nn : Mm;
    __shared__ int buf[1024];
    __shared__ int carry;
    int t = threadIdx.x;
    if (t == 0) carry = 0;
    __syncthreads();
    for (int base = 0; base < n; base += 1024) {
        int v = (base + t < n) ? cnt[base + t] : 0;
        buf[t] = v;
        __syncthreads();
        for (int off = 1; off < 1024; off <<= 1) {
            int x = (t >= off) ? buf[t - off] : 0;
            __syncthreads();
            buf[t] += x;
            __syncthreads();
        }
        int excl = buf[t] - v + carry;
        if (base + t < n) { start[base + t] = excl; cursor[base + t] = excl; }
        __syncthreads();
        if (t == 1023) carry += buf[1023];
        __syncthreads();
    }
    if (t == 0) start[n] = carry;
}

__global__ void k_fill(const int* __restrict__ nidx, const int* __restrict__ eidx,
                       int* __restrict__ ecur, int* __restrict__ elist,
                       int* __restrict__ ncur, int* __restrict__ nlist) {
    int i = blockIdx.x * blockDim.x + threadIdx.x;
    if (i < NNZv) {
        int e = eidx[i], n = nidx[i];
        elist[atomicAdd(&ecur[e], 1)] = n;
        nlist[atomicAdd(&ncur[n], 1)] = e;
    }
}

__global__ void k_dinv(const int* __restrict__ nstart, const int* __restrict__ nlist,
                       const int* __restrict__ estart, float* __restrict__ dinv) {
    int n = blockIdx.x * blockDim.x + threadIdx.x;
    if (n >= Nn) return;
    int s = nstart[n], e = nstart[n + 1];
    float sum = 0.f;
    for (int j = s; j < e; j++) {
        int ed = nlist[j];
        sum += (float)(estart[ed + 1] - estart[ed]);
    }
    dinv[n] = (sum > 0.f) ? 1.f / sum : 1.f;
}

// ---------------- CSR segment-sum gather ----------------
template <int D>
__global__ void k_gather(const float4* __restrict__ src, const int* __restrict__ start,
                         const int* __restrict__ list, float4* __restrict__ dst, int rows) {
    constexpr int WPR = D / 128;
    int gw = (blockIdx.x * blockDim.x + threadIdx.x) >> 5;
    int lane = threadIdx.x & 31;
    int row = gw / WPR;
    if (row >= rows) return;
    int col = (gw % WPR) * 32 + lane;
    int s = __ldg(&start[row]), e = __ldg(&start[row + 1]);
    float4 acc = make_float4(0.f, 0.f, 0.f, 0.f);
    for (int j0 = s; j0 < e; j0 += 32) {
        int cnt = min(32, e - j0);
        int id = 0;
        if (lane < cnt) id = __ldg(&list[j0 + lane]);
        for (int jj = 0; jj < cnt; jj++) {
            int r = __shfl_sync(0xffffffffu, id, jj);
            float4 v = __ldg(&src[(size_t)r * (D / 4) + col]);
            acc.x += v.x; acc.y += v.y; acc.z += v.z; acc.w += v.w;
        }
    }
    dst[(size_t)row * (D / 4) + col] = acc;
}

// gather with on-the-fly BN+relu applied to src rows (D=256)
__global__ void k_gather_bn(const float4* __restrict__ src, const int* __restrict__ start,
                            const int* __restrict__ list, const float* __restrict__ bn,
                            float4* __restrict__ dst, int rows) {
    int gw = (blockIdx.x * blockDim.x + threadIdx.x) >> 5;
    int lane = threadIdx.x & 31;
    int row = gw >> 1;
    if (row >= rows) return;
    int col = ((gw & 1) << 5) + lane;   // float4 col 0..63
    float4 sc = ((const float4*)bn)[col];
    float4 sh = ((const float4*)(bn + HID))[col];
    int s = __ldg(&start[row]), e = __ldg(&start[row + 1]);
    float4 acc = make_float4(0.f, 0.f, 0.f, 0.f);
    for (int j0 = s; j0 < e; j0 += 32) {
        int cnt = min(32, e - j0);
        int id = 0;
        if (lane < cnt) id = __ldg(&list[j0 + lane]);
        for (int jj = 0; jj < cnt; jj++) {
            int r = __shfl_sync(0xffffffffu, id, jj);
            float4 v = __ldg(&src[(size_t)r * 64 + col]);
            acc.x += fmaxf(v.x * sc.x + sh.x, 0.f);
            acc.y += fmaxf(v.y * sc.y + sh.y, 0.f);
            acc.z += fmaxf(v.z * sc.z + sh.z, 0.f);
            acc.w += fmaxf(v.w * sc.w + sh.w, 0.f);
        }
    }
    dst[(size_t)row * 64 + col] = acc;
}

// ---------------- GEMM via fma.rn.f32x2 ----------------
// C[M x Nc] = act(A) @ B + bias ; tile 64(M) x 128(N), 128 threads, 8x8/thread.
// BNA: apply relu(a*sc+sh) to A elements (per-column affine) while loading.
template <bool BNA>
__global__ __launch_bounds__(128) void k_gemm2(
    const float* __restrict__ A, const float* __restrict__ B,
    const float* __restrict__ bias, const float* __restrict__ bn,
    float* __restrict__ C, int K, int Nc) {
    __shared__ float As[16][68];     // [k][row]
    __shared__ float2 Bs[16][130];   // [k][col], value duplicated
    const int t = threadIdx.x;
    const int tx = t & 15, ty = t >> 4;
    const int row0 = blockIdx.y * 64, col0 = blockIdx.x * 128;

    ull acc[4][8];
#pragma unroll
    for (int i = 0; i < 4; i++)
#pragma unroll
        for (int j = 0; j < 8; j++) acc[i][j] = 0ull;

    const int ar = t >> 1;          // A fill: row 0..63
    const int ak = (t & 1) * 8;     // k offset 0 or 8
    const int bk = t >> 3;          // B fill: k 0..15
    const int bc = (t & 7) * 16;    // col offset

    for (int kb = 0; kb < K; kb += 16) {
#pragma unroll
        for (int q = 0; q < 2; q++) {
            float4 v = *(const float4*)(A + (size_t)(row0 + ar) * K + kb + ak + q * 4);
            if (BNA) {
                float4 sc = *(const float4*)(bn + kb + ak + q * 4);
                float4 sh = *(const float4*)(bn + HID + kb + ak + q * 4);
                v.x = fmaxf(v.x * sc.x + sh.x, 0.f);
                v.y = fmaxf(v.y * sc.y + sh.y, 0.f);
                v.z = fmaxf(v.z * sc.z + sh.z, 0.f);
                v.w = fmaxf(v.w * sc.w + sh.w, 0.f);
            }
            As[ak + q * 4 + 0][ar] = v.x;
            As[ak + q * 4 + 1][ar] = v.y;
            As[ak + q * 4 + 2][ar] = v.z;
            As[ak + q * 4 + 3][ar] = v.w;
        }
#pragma unroll
        for (int q = 0; q < 4; q++) {
            float4 v = *(const float4*)(B + (size_t)(kb + bk) * Nc + col0 + bc + q * 4);
            Bs[bk][bc + q * 4 + 0] = make_float2(v.x, v.x);
            Bs[bk][bc + q * 4 + 1] = make_float2(v.y, v.y);
            Bs[bk][bc + q * 4 + 2] = make_float2(v.z, v.z);
            Bs[bk][bc + q * 4 + 3] = make_float2(v.w, v.w);
        }
        __syncthreads();
#pragma unroll
        for (int k = 0; k < 16; k++) {
            float4 a0 = *(const float4*)&As[k][ty * 8];
            float4 a1 = *(const float4*)&As[k][ty * 8 + 4];
            ull ap[4];
            ap[0] = pk2(a0.x, a0.y);
            ap[1] = pk2(a0.z, a0.w);
            ap[2] = pk2(a1.x, a1.y);
            ap[3] = pk2(a1.z, a1.w);
#pragma unroll
            for (int s = 0; s < 4; s++) {
                float4 braw = *(const float4*)&Bs[k][tx * 2 + 32 * s];
                ull b0 = ((const ull*)&braw)[0];
                ull b1 = ((const ull*)&braw)[1];
#pragma unroll
                for (int rp = 0; rp < 4; rp++) {
                    ffma2(acc[rp][s * 2 + 0], ap[rp], b0);
                    ffma2(acc[rp][s * 2 + 1], ap[rp], b1);
                }
            }
        }
        __syncthreads();
    }
    // epilogue
#pragma unroll
    for (int s = 0; s < 4; s++) {
        int c = col0 + tx * 2 + 32 * s;
        float2 bb = *(const float2*)&bias[c];
#pragma unroll
        for (int rp = 0; rp < 4; rp++) {
            float2 v0 = upk(acc[rp][s * 2 + 0]);   // (row even, row odd) for col c
            float2 v1 = upk(acc[rp][s * 2 + 1]);   // for col c+1
            int r0 = row0 + ty * 8 + rp * 2;
            float2 o0 = make_float2(v0.x + bb.x, v1.x + bb.y);
            float2 o1 = make_float2(v0.y + bb.x, v1.y + bb.y);
            *(float2*)(C + (size_t)r0 * Nc + c) = o0;
            *(float2*)(C + (size_t)(r0 + 1) * Nc + c) = o1;
        }
    }
}

// ---------------- BatchNorm stats + params ----------------
#define BN_ROWS 50
__global__ void k_bnstats(const float* __restrict__ x, float* __restrict__ stats) {
    int c = threadIdx.x;
    int r0 = blockIdx.x * BN_ROWS;
    float s = 0.f, q = 0.f;
#pragma unroll 5
    for (int r = 0; r < BN_ROWS; r++) {
        float v = x[(size_t)(r0 + r) * HID + c];
        s += v;
        q += v * v;
    }
    atomicAdd(&stats[c], s);
    atomicAdd(&stats[HID + c], q);
}

// consumes stats -> (sc, sh), then re-zeroes stats for next use
__global__ void k_bnparams(float* __restrict__ stats, const float* __restrict__ g,
                           const float* __restrict__ b, float* __restrict__ bn) {
    int c = threadIdx.x;
    float mean = stats[c] * (1.f / Nn);
    float var = stats[HID + c] * (1.f / Nn) - mean * mean;
    float sc = g[c] * rsqrtf(var + BN_EPS);
    bn[c] = sc;
    bn[HID + c] = b[c] - mean * sc;
    stats[c] = 0.f;
    stats[HID + c] = 0.f;
}

// ---------------- head + readout ----------------
__global__ void k_head(const float* __restrict__ p0, const float* __restrict__ p1,
                       const float* __restrict__ dinv,
                       const float* __restrict__ W, const float* __restrict__ hb,
                       float* __restrict__ out) {
    int wid = (blockIdx.x * blockDim.x + threadIdx.x) >> 5;
    int lane = threadIdx.x & 31;
    if (wid >= Nn) return;
    float acc[NCLS] = {};
    const float* r0 = p0 + (size_t)wid * HID;
    const float* r1 = p1 + (size_t)wid * HID;
    for (int k = lane; k < HID; k += 32) {
        float v = r0[k];
        const float* w = W + (size_t)k * NCLS;
#pragma unroll
        for (int c = 0; c < NCLS; c++) acc[c] += v * w[c];
        float v2 = r1[k];
        const float* w2 = W + (size_t)(HID + k) * NCLS;
#pragma unroll
        for (int c = 0; c < NCLS; c++) acc[c] += v2 * w2[c];
    }
#pragma unroll
    for (int o = 16; o > 0; o >>= 1)
#pragma unroll
        for (int c = 0; c < NCLS; c++) acc[c] += __shfl_down_sync(0xffffffffu, acc[c], o);
    if (lane == 0) {
        float d = dinv[wid];
#pragma unroll
        for (int c = 0; c < NCLS; c++) out[(size_t)wid * NCLS + c] = acc[c] * d + hb[c];
    }
}

__global__ void k_seg(const float* __restrict__ out, const int* __restrict__ batch,
                      float* __restrict__ ssum, float* __restrict__ scnt) {
    int n = blockIdx.x * blockDim.x + threadIdx.x;
    if (n >= Nn) return;
    int b = batch[n];
    atomicAdd(&scnt[b], 1.f);
#pragma unroll
    for (int c = 0; c < NCLS; c++) atomicAdd(&ssum[b * NCLS + c], out[(size_t)n * NCLS + c]);
}

__global__ void k_fin(const float* __restrict__ ssum, const float* __restrict__ scnt,
                      float* __restrict__ dout) {
    int t = blockIdx.x * blockDim.x + threadIdx.x;
    if (t < NG * NCLS) {
        int gidx = t / NCLS;
        dout[t] = ssum[t] / fmaxf(scnt[gidx], 1.f);
    }
}

// ---------------- host ----------------
extern "C" void kernel_launch(void* const* d_in, const int* in_sizes, int n_in,
                              void* d_out, int out_size) {
    const float* X = (const float*)d_in[0];
    const int* node_idx = (const int*)d_in[1];
    const int* edge_idx = (const int*)d_in[2];
    const int* all_batch = (const int*)d_in[3];
    const float* W1_0 = (const float*)d_in[4];
    const float* b1_0 = (const float*)d_in[5];
    const float* g1_0 = (const float*)d_in[6];
    const float* be1_0 = (const float*)d_in[7];
    const float* W2_0 = (const float*)d_in[8];
    const float* b2_0 = (const float*)d_in[9];
    const float* bng_0 = (const float*)d_in[10];
    const float* bnb_0 = (const float*)d_in[11];
    const float* W1_1 = (const float*)d_in[12];
    const float* b1_1 = (const float*)d_in[13];
    const float* g1_1 = (const float*)d_in[14];
    const float* be1_1 = (const float*)d_in[15];
    const float* W2_1 = (const float*)d_in[16];
    const float* b2_1 = (const float*)d_in[17];
    const float* bng_1 = (const float*)d_in[18];
    const float* bnb_1 = (const float*)d_in[19];
    const float* head_W = (const float*)d_in[20];
    const float* head_b = (const float*)d_in[21];

    float *E, *P0, *P1, *Z, *h0, *h1, *dinv, *stats, *bn, *outp, *ssum, *scnt;
    int *ecnt, *estart, *ecur, *elist, *ncnt, *nstart, *ncur, *nlist;
    cudaGetSymbolAddress((void**)&E, g_E);
    cudaGetSymbolAddress((void**)&P0, g_P0);
    cudaGetSymbolAddress((void**)&P1, g_P1);
    cudaGetSymbolAddress((void**)&Z, g_Z);
    cudaGetSymbolAddress((void**)&h0, g_h0);
    cudaGetSymbolAddress((void**)&h1, g_h1);
    cudaGetSymbolAddress((void**)&dinv, g_dinv);
    cudaGetSymbolAddress((void**)&stats, g_stats);
    cudaGetSymbolAddress((void**)&bn, g_bn);
    cudaGetSymbolAddress((void**)&outp, g_out);
    cudaGetSymbolAddress((void**)&ssum, g_segsum);
    cudaGetSymbolAddress((void**)&scnt, g_segcnt);
    cudaGetSymbolAddress((void**)&ecnt, g_ecnt);
    cudaGetSymbolAddress((void**)&estart, g_estart);
    cudaGetSymbolAddress((void**)&ecur, g_ecur);
    cudaGetSymbolAddress((void**)&elist, g_elist);
    cudaGetSymbolAddress((void**)&ncnt, g_ncnt);
    cudaGetSymbolAddress((void**)&nstart, g_nstart);
    cudaGetSymbolAddress((void**)&ncur, g_ncur);
    cudaGetSymbolAddress((void**)&nlist, g_nlist);

    const int SB = 256;
    const int nnz_blocks = (NNZv + SB - 1) / SB;
    const int ge128 = (Mm * 32 + SB - 1) / SB;
    const int gn128 = (Nn * 32 + SB - 1) / SB;
    const int ge256 = (Mm * 64 + SB - 1) / SB;
    const int gn256 = (Nn * 64 + SB - 1) / SB;
    dim3 gemm_grid(HID / 128, Nn / 64);

    // ---- CSR build ----
    k_init<<<64, SB>>>(ecnt, ncnt, stats);
    k_hist<<<nnz_blocks, SB>>>(node_idx, edge_idx, ecnt, ncnt);
    k_scan2<<<2, 1024>>>(ecnt, estart, ecur, ncnt, nstart, ncur);
    k_fill<<<nnz_blocks, SB>>>(node_idx, edge_idx, ecur, elist, ncur, nlist);
    k_dinv<<<(Nn + SB - 1) / SB, SB>>>(nstart, nlist, estart, dinv);

    // ---- layer 0 (Pa in P1 buffer, [N,128]) ----
    k_gather<128><<<ge128, SB>>>((const float4*)X, estart, elist, (float4*)E, Mm);
    k_gather<128><<<gn128, SB>>>((const float4*)E, nstart, nlist, (float4*)P1, Nn);
    k_gemm2<false><<<gemm_grid, 128>>>(P1, W1_0, b1_0, bn, Z, FT, HID);
    k_bnstats<<<Nn / BN_ROWS, HID>>>(Z, stats);
    k_bnparams<<<1, HID>>>(stats, g1_0, be1_0, bn);
    k_gemm2<true><<<gemm_grid, 128>>>(Z, W2_0, b2_0, bn, h0, HID, HID);
    k_bnstats<<<Nn / BN_ROWS, HID>>>(h0, stats);
    k_bnparams<<<1, HID>>>(stats, bng_0, bnb_0, bn);

    // ---- layer 1 (P0 = H(Ht(bn(h0))), reused for head) ----
    k_gather_bn<<<ge256, SB>>>((const float4*)h0, estart, elist, bn, (float4*)E, Mm);
    k_gather<256><<<gn256, SB>>>((const float4*)E, nstart, nlist, (float4*)P0, Nn);
    k_gemm2<false><<<gemm_grid, 128>>>(P0, W1_1, b1_1, bn, Z, HID, HID);
    k_bnstats<<<Nn / BN_ROWS, HID>>>(Z, stats);
    k_bnparams<<<1, HID>>>(stats, g1_1, be1_1, bn);
    k_gemm2<true><<<gemm_grid, 128>>>(Z, W2_1, b2_1, bn, h1, HID, HID);
    k_bnstats<<<Nn / BN_ROWS, HID>>>(h1, stats);
    k_bnparams<<<1, HID>>>(stats, bng_1, bnb_1, bn);

    // ---- pooling for h1 ----
    k_gather_bn<<<ge256, SB>>>((const float4*)h1, estart, elist, bn, (float4*)E, Mm);
    k_gather<256><<<gn256, SB>>>((const float4*)E, nstart, nlist, (float4*)P1, Nn);

    // ---- head + readout ----
    k_head<<<(Nn * 32 + SB - 1) / SB, SB>>>(P0, P1, dinv, head_W, head_b, outp);
    k_zerof<<<(NG * NCLS + NG + SB - 1) / SB, SB>>>(ssum, NG * NCLS + NG);  // ssum+scnt contiguous? no — zero separately
    k_zerof<<<1, NG>>>(scnt, NG);
    k_seg<<<(Nn + SB - 1) / SB, SB>>>(outp, all_batch, ssum, scnt);
    k_fin<<<(NG * NCLS + SB - 1) / SB, SB>>>(ssum, scnt, (float*)d_out);
}

// round 4
// speedup vs baseline: 1.3404x; 1.3404x over previous
#include <cuda_runtime.h>

#define Nn 40000
#define NPAD 40064
#define Mm 10000
#define NNZv 400000
#define FT 128
#define HID 256
#define NCLS 10
#define NG 128
#define BN_EPS 1e-5f

// ---------------- scratch ----------------
__device__ float g_E[(size_t)Mm * HID];
__device__ float g_P0[(size_t)NPAD * HID];   // H(Ht(bn(h0))): layer1 input AND pooled h0
__device__ float g_P1[(size_t)NPAD * HID];   // pooled h1; reused as Pa [N,128] in layer0
__device__ float g_Z[(size_t)NPAD * HID];
__device__ float g_h0[(size_t)NPAD * HID];
__device__ float g_h1[(size_t)NPAD * HID];
__device__ float g_dinv[Nn];
__device__ float g_stats[2 * HID];
__device__ float g_bn[2 * HID];              // sc | sh
__device__ float g_out[(size_t)Nn * NCLS];
__device__ float g_segsum[NG * NCLS];
__device__ float g_segcnt[NG];
__device__ int g_ecnt[Mm];
__device__ int g_estart[Mm + 1];
__device__ int g_ecur[Mm];
__device__ int g_elist[NNZv];
__device__ int g_ncnt[Nn];
__device__ int g_nstart[Nn + 1];
__device__ int g_ncur[Nn];
__device__ int g_nlist[NNZv];

// ---------------- init / utility ----------------
__global__ void k_init(int* ecnt, int* ncnt, float* stats) {
    int i = blockIdx.x * blockDim.x + threadIdx.x;
    int stride = gridDim.x * blockDim.x;
    for (int j = i; j < Mm; j += stride) ecnt[j] = 0;
    for (int j = i; j < Nn; j += stride) ncnt[j] = 0;
    if (i < 2 * HID) stats[i] = 0.f;
}
__global__ void k_zerof(float* p, int n) {
    int i = blockIdx.x * blockDim.x + threadIdx.x;
    if (i < n) p[i] = 0.f;
}

// ---------------- CSR build ----------------
__global__ void k_hist(const int* __restrict__ nidx, const int* __restrict__ eidx,
                       int* __restrict__ ecnt, int* __restrict__ ncnt) {
    int i = blockIdx.x * blockDim.x + threadIdx.x;
    if (i < NNZv) {
        atomicAdd(&ecnt[eidx[i]], 1);
        atomicAdd(&ncnt[nidx[i]], 1);
    }
}

__global__ void k_scan2(const int* __restrict__ ecnt, int* __restrict__ estart, int* __restrict__ ecur,
                        const int* __restrict__ ncnt, int* __restrict__ nstart, int* __restrict__ ncur) {
    const int* cnt = blockIdx.x ? ncnt : ecnt;
    int* start = blockIdx.x ? nstart : estart;
    int* cursor = blockIdx.x ? ncur : ecur;
    int n = blockIdx.x ? Nn : Mm;
    __shared__ int buf[1024];
    __shared__ int carry;
    int t = threadIdx.x;
    if (t == 0) carry = 0;
    __syncthreads();
    for (int base = 0; base < n; base += 1024) {
        int v = (base + t < n) ? cnt[base + t] : 0;
        buf[t] = v;
        __syncthreads();
        for (int off = 1; off < 1024; off <<= 1) {
            int x = (t >= off) ? buf[t - off] : 0;
            __syncthreads();
            buf[t] += x;
            __syncthreads();
        }
        int excl = buf[t] - v + carry;
        if (base + t < n) { start[base + t] = excl; cursor[base + t] = excl; }
        __syncthreads();
        if (t == 1023) carry += buf[1023];
        __syncthreads();
    }
    if (t == 0) start[n] = carry;
}

__global__ void k_fill(const int* __restrict__ nidx, const int* __restrict__ eidx,
                       int* __restrict__ ecur, int* __restrict__ elist,
                       int* __restrict__ ncur, int* __restrict__ nlist) {
    int i = blockIdx.x * blockDim.x + threadIdx.x;
    if (i < NNZv) {
        int e = eidx[i], n = nidx[i];
        elist[atomicAdd(&ecur[e], 1)] = n;
        nlist[atomicAdd(&ncur[n], 1)] = e;
    }
}

__global__ void k_dinv(const int* __restrict__ nstart, const int* __restrict__ nlist,
                       const int* __restrict__ estart, float* __restrict__ dinv) {
    int n = blockIdx.x * blockDim.x + threadIdx.x;
    if (n >= Nn) return;
    int s = nstart[n], e = nstart[n + 1];
    float sum = 0.f;
    for (int j = s; j < e; j++) {
        int ed = nlist[j];
        sum += (float)(estart[ed + 1] - estart[ed]);
    }
    dinv[n] = (sum > 0.f) ? 1.f / sum : 1.f;
}

// ---------------- CSR segment-sum gather ----------------
template <int D>
__global__ void k_gather(const float4* __restrict__ src, const int* __restrict__ start,
                         const int* __restrict__ list, float4* __restrict__ dst, int rows) {
    constexpr int WPR = D / 128;
    int gw = (blockIdx.x * blockDim.x + threadIdx.x) >> 5;
    int lane = threadIdx.x & 31;
    int row = gw / WPR;
    if (row >= rows) return;
    int col = (gw % WPR) * 32 + lane;
    int s = __ldg(&start[row]), e = __ldg(&start[row + 1]);
    float4 acc = make_float4(0.f, 0.f, 0.f, 0.f);
    for (int j0 = s; j0 < e; j0 += 32) {
        int cnt = min(32, e - j0);
        int id = 0;
        if (lane < cnt) id = __ldg(&list[j0 + lane]);
        for (int jj = 0; jj < cnt; jj++) {
            int r = __shfl_sync(0xffffffffu, id, jj);
            float4 v = __ldg(&src[(size_t)r * (D / 4) + col]);
            acc.x += v.x; acc.y += v.y; acc.z += v.z; acc.w += v.w;
        }
    }
    dst[(size_t)row * (D / 4) + col] = acc;
}

// gather with on-the-fly BN+relu applied to src rows (D=256)
__global__ void k_gather_bn(const float4* __restrict__ src, const int* __restrict__ start,
                            const int* __restrict__ list, const float* __restrict__ bn,
                            float4* __restrict__ dst, int rows) {
    int gw = (blockIdx.x * blockDim.x + threadIdx.x) >> 5;
    int lane = threadIdx.x & 31;
    int row = gw >> 1;
    if (row >= rows) return;
    int col = ((gw & 1) << 5) + lane;
    float4 sc = ((const float4*)bn)[col];
    float4 sh = ((const float4*)(bn + HID))[col];
    int s = __ldg(&start[row]), e = __ldg(&start[row + 1]);
    float4 acc = make_float4(0.f, 0.f, 0.f, 0.f);
    for (int j0 = s; j0 < e; j0 += 32) {
        int cnt = min(32, e - j0);
        int id = 0;
        if (lane < cnt) id = __ldg(&list[j0 + lane]);
        for (int jj = 0; jj < cnt; jj++) {
            int r = __shfl_sync(0xffffffffu, id, jj);
            float4 v = __ldg(&src[(size_t)r * 64 + col]);
            acc.x += fmaxf(v.x * sc.x + sh.x, 0.f);
            acc.y += fmaxf(v.y * sc.y + sh.y, 0.f);
            acc.z += fmaxf(v.z * sc.z + sh.z, 0.f);
            acc.w += fmaxf(v.w * sc.w + sh.w, 0.f);
        }
    }
    dst[(size_t)row * 64 + col] = acc;
}

// ---------------- tf32x3 tensor-core GEMM ----------------
__device__ __forceinline__ unsigned tf32r(float f) {
    unsigned r;
    asm("cvt.rna.tf32.f32 %0, %1;" : "=r"(r) : "f"(f));
    return r;
}
__device__ __forceinline__ void mma8(float* c, const unsigned* a, unsigned b0, unsigned b1) {
    asm volatile(
        "mma.sync.aligned.m16n8k8.row.col.f32.tf32.tf32.f32 "
        "{%0,%1,%2,%3}, {%4,%5,%6,%7}, {%8,%9}, {%0,%1,%2,%3};"
        : "+f"(c[0]), "+f"(c[1]), "+f"(c[2]), "+f"(c[3])
        : "r"(a[0]), "r"(a[1]), "r"(a[2]), "r"(a[3]), "r"(b0), "r"(b1));
}

// C[Mrows x Nc] = act(A) @ B + bias. Block tile 128x128, 256 thr (8 warps, 32x64 each).
// A/B split hi/lo at smem store -> 3 mma passes (hi*hi + lo*hi + hi*lo) ~ fp32 precision.
template <bool BNA>
__global__ __launch_bounds__(256) void k_gemm_tc(
    const float* __restrict__ A, const float* __restrict__ B,
    const float* __restrict__ bias, const float* __restrict__ bn,
    float* __restrict__ C, int K, int Nc, int Mrows) {
    __shared__ unsigned Ah[16][132], Al[16][132];
    __shared__ unsigned Bh[16][132], Bl[16][132];
    const int t = threadIdx.x;
    const int wid = t >> 5, lane = t & 31;
    const int wm = wid & 3, wn = wid >> 2;
    const int row0 = blockIdx.y * 128, col0 = blockIdx.x * 128;

    float acc[2][8][4];
#pragma unroll
    for (int i = 0; i < 2; i++)
#pragma unroll
        for (int j = 0; j < 8; j++)
#pragma unroll
            for (int r = 0; r < 4; r++) acc[i][j][r] = 0.f;

    const int ar = t >> 1;        // A fill: row 0..127
    const int ak = (t & 1) * 8;   // k offset 0/8
    const int bk = t >> 4;        // B fill: k 0..15
    const int bc = (t & 15) * 8;  // col offset

    for (int kb = 0; kb < K; kb += 16) {
        // A 128x16 -> hi/lo
#pragma unroll
        for (int q = 0; q < 2; q++) {
            float4 v = *(const float4*)(A + (size_t)(row0 + ar) * K + kb + ak + q * 4);
            if (BNA) {
                float4 sc = *(const float4*)(bn + kb + ak + q * 4);
                float4 sh = *(const float4*)(bn + HID + kb + ak + q * 4);
                v.x = fmaxf(v.x * sc.x + sh.x, 0.f);
                v.y = fmaxf(v.y * sc.y + sh.y, 0.f);
                v.z = fmaxf(v.z * sc.z + sh.z, 0.f);
                v.w = fmaxf(v.w * sc.w + sh.w, 0.f);
            }
            float vv[4] = {v.x, v.y, v.z, v.w};
#pragma unroll
            for (int j = 0; j < 4; j++) {
                unsigned hi = tf32r(vv[j]);
                float lo = vv[j] - __uint_as_float(hi);
                Ah[ak + q * 4 + j][ar] = hi;
                Al[ak + q * 4 + j][ar] = tf32r(lo);
            }
        }
        // B 16x128 -> hi/lo (contiguous in n)
#pragma unroll
        for (int q = 0; q < 2; q++) {
            float4 v = *(const float4*)(B + (size_t)(kb + bk) * Nc + col0 + bc + q * 4);
            float vv[4] = {v.x, v.y, v.z, v.w};
            unsigned h[4], l[4];
#pragma unroll
            for (int j = 0; j < 4; j++) {
                h[j] = tf32r(vv[j]);
                l[j] = tf32r(vv[j] - __uint_as_float(h[j]));
            }
            *(uint4*)&Bh[bk][bc + q * 4] = make_uint4(h[0], h[1], h[2], h[3]);
            *(uint4*)&Bl[bk][bc + q * 4] = make_uint4(l[0], l[1], l[2], l[3]);
        }
        __syncthreads();

#pragma unroll
        for (int ks = 0; ks < 2; ks++) {
            const int k0 = ks * 8 + (lane & 3);
            const int mb = wm * 32 + (lane >> 2);
            unsigned ah[2][4], al[2][4];
#pragma unroll
            for (int mt = 0; mt < 2; mt++) {
                int m = mb + mt * 16;
                ah[mt][0] = Ah[k0][m];     ah[mt][1] = Ah[k0][m + 8];
                ah[mt][2] = Ah[k0 + 4][m]; ah[mt][3] = Ah[k0 + 4][m + 8];
                al[mt][0] = Al[k0][m];     al[mt][1] = Al[k0][m + 8];
                al[mt][2] = Al[k0 + 4][m]; al[mt][3] = Al[k0 + 4][m + 8];
            }
#pragma unroll
            for (int nt = 0; nt < 8; nt++) {
                int n = wn * 64 + nt * 8 + (lane >> 2);
                unsigned bh0 = Bh[k0][n], bh1 = Bh[k0 + 4][n];
                unsigned bl0 = Bl[k0][n], bl1 = Bl[k0 + 4][n];
#pragma unroll
                for (int mt = 0; mt < 2; mt++) {
                    mma8(acc[mt][nt], ah[mt], bh0, bh1);
                    mma8(acc[mt][nt], al[mt], bh0, bh1);
                    mma8(acc[mt][nt], ah[mt], bl0, bl1);
                }
            }
        }
        __syncthreads();
    }
    // epilogue
#pragma unroll
    for (int mt = 0; mt < 2; mt++) {
#pragma unroll
        for (int nt = 0; nt < 8; nt++) {
            int r = row0 + wm * 32 + mt * 16 + (lane >> 2);
            int c = col0 + wn * 64 + nt * 8 + 2 * (lane & 3);
            float2 bb = *(const float2*)&bias[c];
            if (r < Mrows)
                *(float2*)(C + (size_t)r * Nc + c) =
                    make_float2(acc[mt][nt][0] + bb.x, acc[mt][nt][1] + bb.y);
            if (r + 8 < Mrows)
                *(float2*)(C + (size_t)(r + 8) * Nc + c) =
                    make_float2(acc[mt][nt][2] + bb.x, acc[mt][nt][3] + bb.y);
        }
    }
}

// ---------------- BatchNorm stats + params ----------------
#define BN_ROWS 50
__global__ void k_bnstats(const float* __restrict__ x, float* __restrict__ stats) {
    int c = threadIdx.x;
    int r0 = blockIdx.x * BN_ROWS;
    float s = 0.f, q = 0.f;
#pragma unroll 5
    for (int r = 0; r < BN_ROWS; r++) {
        float v = x[(size_t)(r0 + r) * HID + c];
        s += v;
        q += v * v;
    }
    atomicAdd(&stats[c], s);
    atomicAdd(&stats[HID + c], q);
}

__global__ void k_bnparams(float* __restrict__ stats, const float* __restrict__ g,
                           const float* __restrict__ b, float* __restrict__ bn) {
    int c = threadIdx.x;
    float mean = stats[c] * (1.f / Nn);
    float var = stats[HID + c] * (1.f / Nn) - mean * mean;
    float sc = g[c] * rsqrtf(var + BN_EPS);
    bn[c] = sc;
    bn[HID + c] = b[c] - mean * sc;
    stats[c] = 0.f;
    stats[HID + c] = 0.f;
}

// ---------------- head + readout ----------------
__global__ void k_head(const float* __restrict__ p0, const float* __restrict__ p1,
                       const float* __restrict__ dinv,
                       const float* __restrict__ W, const float* __restrict__ hb,
                       float* __restrict__ out) {
    int wid = (blockIdx.x * blockDim.x + threadIdx.x) >> 5;
    int lane = threadIdx.x & 31;
    if (wid >= Nn) return;
    float acc[NCLS] = {};
    const float* r0 = p0 + (size_t)wid * HID;
    const float* r1 = p1 + (size_t)wid * HID;
    for (int k = lane; k < HID; k += 32) {
        float v = r0[k];
        const float* w = W + (size_t)k * NCLS;
#pragma unroll
        for (int c = 0; c < NCLS; c++) acc[c] += v * w[c];
        float v2 = r1[k];
        const float* w2 = W + (size_t)(HID + k) * NCLS;
#pragma unroll
        for (int c = 0; c < NCLS; c++) acc[c] += v2 * w2[c];
    }
#pragma unroll
    for (int o = 16; o > 0; o >>= 1)
#pragma unroll
        for (int c = 0; c < NCLS; c++) acc[c] += __shfl_down_sync(0xffffffffu, acc[c], o);
    if (lane == 0) {
        float d = dinv[wid];
#pragma unroll
        for (int c = 0; c < NCLS; c++) out[(size_t)wid * NCLS + c] = acc[c] * d + hb[c];
    }
}

__global__ void k_seg(const float* __restrict__ out, const int* __restrict__ batch,
                      float* __restrict__ ssum, float* __restrict__ scnt) {
    int n = blockIdx.x * blockDim.x + threadIdx.x;
    if (n >= Nn) return;
    int b = batch[n];
    atomicAdd(&scnt[b], 1.f);
#pragma unroll
    for (int c = 0; c < NCLS; c++) atomicAdd(&ssum[b * NCLS + c], out[(size_t)n * NCLS + c]);
}

__global__ void k_fin(const float* __restrict__ ssum, const float* __restrict__ scnt,
                      float* __restrict__ dout) {
    int t = blockIdx.x * blockDim.x + threadIdx.x;
    if (t < NG * NCLS) {
        int gidx = t / NCLS;
        dout[t] = ssum[t] / fmaxf(scnt[gidx], 1.f);
    }
}

// ---------------- host ----------------
extern "C" void kernel_launch(void* const* d_in, const int* in_sizes, int n_in,
                              void* d_out, int out_size) {
    const float* X = (const float*)d_in[0];
    const int* node_idx = (const int*)d_in[1];
    const int* edge_idx = (const int*)d_in[2];
    const int* all_batch = (const int*)d_in[3];
    const float* W1_0 = (const float*)d_in[4];
    const float* b1_0 = (const float*)d_in[5];
    const float* g1_0 = (const float*)d_in[6];
    const float* be1_0 = (const float*)d_in[7];
    const float* W2_0 = (const float*)d_in[8];
    const float* b2_0 = (const float*)d_in[9];
    const float* bng_0 = (const float*)d_in[10];
    const float* bnb_0 = (const float*)d_in[11];
    const float* W1_1 = (const float*)d_in[12];
    const float* b1_1 = (const float*)d_in[13];
    const float* g1_1 = (const float*)d_in[14];
    const float* be1_1 = (const float*)d_in[15];
    const float* W2_1 = (const float*)d_in[16];
    const float* b2_1 = (const float*)d_in[17];
    const float* bng_1 = (const float*)d_in[18];
    const float* bnb_1 = (const float*)d_in[19];
    const float* head_W = (const float*)d_in[20];
    const float* head_b = (const float*)d_in[21];

    float *E, *P0, *P1, *Z, *h0, *h1, *dinv, *stats, *bn, *outp, *ssum, *scnt;
    int *ecnt, *estart, *ecur, *elist, *ncnt, *nstart, *ncur, *nlist;
    cudaGetSymbolAddress((void**)&E, g_E);
    cudaGetSymbolAddress((void**)&P0, g_P0);
    cudaGetSymbolAddress((void**)&P1, g_P1);
    cudaGetSymbolAddress((void**)&Z, g_Z);
    cudaGetSymbolAddress((void**)&h0, g_h0);
    cudaGetSymbolAddress((void**)&h1, g_h1);
    cudaGetSymbolAddress((void**)&dinv, g_dinv);
    cudaGetSymbolAddress((void**)&stats, g_stats);
    cudaGetSymbolAddress((void**)&bn, g_bn);
    cudaGetSymbolAddress((void**)&outp, g_out);
    cudaGetSymbolAddress((void**)&ssum, g_segsum);
    cudaGetSymbolAddress((void**)&scnt, g_segcnt);
    cudaGetSymbolAddress((void**)&ecnt, g_ecnt);
    cudaGetSymbolAddress((void**)&estart, g_estart);
    cudaGetSymbolAddress((void**)&ecur, g_ecur);
    cudaGetSymbolAddress((void**)&elist, g_elist);
    cudaGetSymbolAddress((void**)&ncnt, g_ncnt);
    cudaGetSymbolAddress((void**)&nstart, g_nstart);
    cudaGetSymbolAddress((void**)&ncur, g_ncur);
    cudaGetSymbolAddress((void**)&nlist, g_nlist);

    const int SB = 256;
    const int nnz_blocks = (NNZv + SB - 1) / SB;
    const int ge128 = (Mm * 32 + SB - 1) / SB;
    const int gn128 = (Nn * 32 + SB - 1) / SB;
    const int ge256 = (Mm * 64 + SB - 1) / SB;
    const int gn256 = (Nn * 64 + SB - 1) / SB;
    dim3 tc_grid(HID / 128, NPAD / 128);   // (2, 313)

    // ---- CSR build ----
    k_init<<<64, SB>>>(ecnt, ncnt, stats);
    k_hist<<<nnz_blocks, SB>>>(node_idx, edge_idx, ecnt, ncnt);
    k_scan2<<<2, 1024>>>(ecnt, estart, ecur, ncnt, nstart, ncur);
    k_fill<<<nnz_blocks, SB>>>(node_idx, edge_idx, ecur, elist, ncur, nlist);
    k_dinv<<<(Nn + SB - 1) / SB, SB>>>(nstart, nlist, estart, dinv);

    // ---- layer 0 (Pa in P1 buffer, [N,128]) ----
    k_gather<128><<<ge128, SB>>>((const float4*)X, estart, elist, (float4*)E, Mm);
    k_gather<128><<<gn128, SB>>>((const float4*)E, nstart, nlist, (float4*)P1, Nn);
    k_gemm_tc<false><<<tc_grid, 256>>>(P1, W1_0, b1_0, bn, Z, FT, HID, Nn);
    k_bnstats<<<Nn / BN_ROWS, HID>>>(Z, stats);
    k_bnparams<<<1, HID>>>(stats, g1_0, be1_0, bn);
    k_gemm_tc<true><<<tc_grid, 256>>>(Z, W2_0, b2_0, bn, h0, HID, HID, Nn);
    k_bnstats<<<Nn / BN_ROWS, HID>>>(h0, stats);
    k_bnparams<<<1, HID>>>(stats, bng_0, bnb_0, bn);

    // ---- layer 1 (P0 = H(Ht(bn(h0))), reused for head) ----
    k_gather_bn<<<ge256, SB>>>((const float4*)h0, estart, elist, bn, (float4*)E, Mm);
    k_gather<256><<<gn256, SB>>>((const float4*)E, nstart, nlist, (float4*)P0, Nn);
    k_gemm_tc<false><<<tc_grid, 256>>>(P0, W1_1, b1_1, bn, Z, HID, HID, Nn);
    k_bnstats<<<Nn / BN_ROWS, HID>>>(Z, stats);
    k_bnparams<<<1, HID>>>(stats, g1_1, be1_1, bn);
    k_gemm_tc<true><<<tc_grid, 256>>>(Z, W2_1, b2_1, bn, h1, HID, HID, Nn);
    k_bnstats<<<Nn / BN_ROWS, HID>>>(h1, stats);
    k_bnparams<<<1, HID>>>(stats, bng_1, bnb_1, bn);

    // ---- pooling for h1 ----
    k_gather_bn<<<ge256, SB>>>((const float4*)h1, estart, elist, bn, (float4*)E, Mm);
    k_gather<256><<<gn256, SB>>>((const float4*)E, nstart, nlist, (float4*)P1, Nn);

    // ---- head + readout ----
    k_head<<<(Nn * 32 + SB - 1) / SB, SB>>>(P0, P1, dinv, head_W, head_b, outp);
    k_zerof<<<(NG * NCLS + SB - 1) / SB, SB>>>(ssum, NG * NCLS);
    k_zerof<<<1, NG>>>(scnt, NG);
    k_seg<<<(Nn + SB - 1) / SB, SB>>>(outp, all_batch, ssum, scnt);
    k_fin<<<(NG * NCLS + SB - 1) / SB, SB>>>(ssum, scnt, (float*)d_out);
}